// round 4
// baseline (speedup 1.0000x reference)
#include <cuda_runtime.h>
#include <cstdint>

// Problem constants (LangevinSDEContiformer: B=1024, S=512, H=64, D_IN=3)
#define BB   1024
#define SS   512
#define HH   64
#define DIN  3
#define SM1  511    // S-1 steps

__device__ float d_sigsc[SM1 * HH];
__device__ float d_hstep[SM1];
__device__ float d_times[SM1];

__global__ void sigma_kernel(const float* __restrict__ ts,
                             const float* __restrict__ Wd1, const float* __restrict__ bd1,
                             const float* __restrict__ Wd2, const float* __restrict__ bd2,
                             const float* __restrict__ minp, const float* __restrict__ maxp)
{
    __shared__ float hh[32];
    int s = blockIdx.x;
    int tid = threadIdx.x;
    float t = ts[(size_t)s * DIN];
    if (tid < 32) hh[tid] = fmaxf(t * Wd1[tid] + bd1[tid], 0.0f);
    __syncthreads();
    float acc = bd2[tid];
    #pragma unroll
    for (int i = 0; i < 32; i++) acc += hh[i] * Wd2[i * HH + tid];
    float sp = fmaxf(acc, 0.0f) + log1pf(expf(-fabsf(acc)));
    float mind = fabsf(minp[0]);
    float maxd = fabsf(maxp[0]);
    float sig = fminf(fmaxf(sp + mind, mind), maxd);
    float hs = ts[(size_t)(s + 1) * DIN] - t;
    d_sigsc[s * HH + tid] = sig * sqrtf(hs);
    if (tid == 0) { d_hstep[s] = hs; d_times[s] = t; }
}

// ---------------------------------------------------------------------------
// Main persistent scan kernel — NO k-split, NO partial buffer.
//   grid = 128 CTAs x 256 threads. CTA owns 8 rows = 2 groups x 4 rows.
//   Each group = 4 warps, synced by its OWN named barrier (groups drift freely).
//   128-col phases (1,3): warp c owns 4 rows x cols [c*32, c*32+32), full k.
//    64-col phases (2,4): warp c owns 2 rows x cols [(c&1)*32, ..), full k.
//   Every warp produces FINAL outputs -> one barrier per phase (4/step).
// ---------------------------------------------------------------------------
#define W1_STRIDE 129
#define W2_STRIDE 65
#define OFF_W1   0                       // 65 x 129 = 8385
#define OFF_W2   (OFF_W1 + 65*129)       // 128 x 65 = 8320
#define OFF_W3   (OFF_W2 + 128*65)       // 64
#define OFF_B1   (OFF_W3 + 64)           // 128
#define OFF_B2   (OFF_B1 + 128)          // 64
#define OFF_Y    (OFF_B2 + 64 + 3)       // 16964 (16B aligned), 8*64
#define OFF_H1   (OFF_Y + 8*64)          // 8*128
#define OFF_G2   (OFF_H1 + 8*128)        // 8*64
#define OFF_G1   (OFF_G2 + 8*64)         // 8*128
#define SMEM_FLOATS (OFF_G1 + 8*128)     // 20036
#define SMEM_BYTES  (SMEM_FLOATS * 4)    // 80144

__device__ __forceinline__ float tanh_fast(float x) {
    float y;
    asm("tanh.approx.f32 %0, %1;" : "=f"(y) : "f"(x));
    return y;
}

__global__ void __launch_bounds__(256, 1)
sde_scan_kernel(const float* __restrict__ ts, const float* __restrict__ noise,
                const float* __restrict__ Wp1, const float* __restrict__ bp1,
                const float* __restrict__ Wp2, const float* __restrict__ bp2,
                const float* __restrict__ Wp3, float* __restrict__ out)
{
    extern __shared__ float sm[];
    float* W1  = sm + OFF_W1;   // [65][129]  Wp1[k][j]
    float* W2  = sm + OFF_W2;   // [128][65]  Wp2[k][j]
    float* W3  = sm + OFF_W3;   // [64]
    float* B1s = sm + OFF_B1;   // [128]
    float* B2s = sm + OFF_B2;   // [64]
    float* Y   = sm + OFF_Y;    // [8][64]
    float* H1s = sm + OFF_H1;   // [8][128]
    float* G2s = sm + OFF_G2;   // [8][64]
    float* G1s = sm + OFF_G1;   // [8][128]

    const int tid  = threadIdx.x;
    const int lane = tid & 31;
    const int wid  = tid >> 5;
    const int grp  = wid >> 2;          // row group 0/1 (4 rows each)
    const int c    = wid & 3;           // warp's role within group
    const int rbase = grp * 4;
    const int rowTop = blockIdx.x * 8;
    const int barid = grp + 1;          // named barrier per group

    const int j1 = c * 32 + lane;            // col for 128-wide phases (1,3)
    const int rp = (c >> 1) * 2;             // row offset for 64-wide phases (2,4)
    const int cb = (c & 1) * 32 + lane;      // col for 64-wide phases (2,4)

    // ---- load weights into shared
    for (int i = tid; i < 65 * 128; i += 256) {
        int k = i >> 7, j = i & 127;
        W1[k * W1_STRIDE + j] = Wp1[i];
    }
    for (int i = tid; i < 128 * 64; i += 256) {
        int k = i >> 6, j = i & 63;
        W2[k * W2_STRIDE + j] = Wp2[i];
    }
    if (tid < 64) { W3[tid] = Wp3[tid]; B2s[tid] = bp2[tid]; }
    if (tid < 128) B1s[tid] = bp1[tid];

    // ---- init y0 and write out[:,0,:]
    #pragma unroll
    for (int q = 0; q < 2; q++) {
        int e = q * 256 + tid;
        int k = e & 63, r8 = e >> 6;
        int b = rowTop + r8;
        float v = (k < DIN) ? ts[(size_t)b * SS * DIN + k] : 0.0f;
        Y[r8 * 64 + k] = v;
        out[((size_t)b * SS) * HH + k] = v;
    }
    __syncthreads();

    for (int s = 0; s < SM1; s++) {
        const float tcur  = d_times[s];
        const float hstep = d_hstep[s];

        // prefetch noise*sigma for the elements THIS thread updates in phase 4
        float zsc[2];
        #pragma unroll
        for (int r = 0; r < 2; r++) {
            int b = rowTop + rbase + rp + r;
            zsc[r] = d_sigsc[s * HH + cb] *
                     noise[((size_t)s * BB + b) * HH + cb];
        }

        // ======== phase 1: h1 = tanh([y,t] @ W1 + b1)  (4 rows x 32 cols) ===
        float h1v[4];
        {
            float acc[4];
            float init = fmaf(tcur, W1[64 * W1_STRIDE + j1], B1s[j1]);
            #pragma unroll
            for (int r = 0; r < 4; r++) acc[r] = init;
            #pragma unroll 8
            for (int kk = 0; kk < 16; kk++) {
                float4 yv[4];
                #pragma unroll
                for (int r = 0; r < 4; r++)
                    yv[r] = *(const float4*)&Y[(rbase + r) * 64 + kk * 4];
                #pragma unroll
                for (int q = 0; q < 4; q++) {
                    float w = W1[(kk * 4 + q) * W1_STRIDE + j1];
                    #pragma unroll
                    for (int r = 0; r < 4; r++)
                        acc[r] = fmaf((&yv[r].x)[q], w, acc[r]);
                }
            }
            #pragma unroll
            for (int r = 0; r < 4; r++) {
                h1v[r] = tanh_fast(acc[r]);
                H1s[(rbase + r) * 128 + j1] = h1v[r];
            }
        }
        asm volatile("bar.sync %0, %1;" :: "r"(barid), "r"(128) : "memory");

        // ======== phase 2: g2 = W3*(1-tanh(h1@W2+b2)^2)  (2 rows x 32 cols) =
        {
            float acc[2];
            float init = B2s[cb];
            acc[0] = init; acc[1] = init;
            #pragma unroll 8
            for (int kk = 0; kk < 32; kk++) {
                float4 hv[2];
                #pragma unroll
                for (int r = 0; r < 2; r++)
                    hv[r] = *(const float4*)&H1s[(rbase + rp + r) * 128 + kk * 4];
                #pragma unroll
                for (int q = 0; q < 4; q++) {
                    float w = W2[(kk * 4 + q) * W2_STRIDE + cb];
                    #pragma unroll
                    for (int r = 0; r < 2; r++)
                        acc[r] = fmaf((&hv[r].x)[q], w, acc[r]);
                }
            }
            float w3 = W3[cb];
            #pragma unroll
            for (int r = 0; r < 2; r++) {
                float h2 = tanh_fast(acc[r]);
                G2s[(rbase + rp + r) * 64 + cb] = w3 * (1.0f - h2 * h2);
            }
        }
        asm volatile("bar.sync %0, %1;" :: "r"(barid), "r"(128) : "memory");

        // ======== phase 3: g1 = (g2 @ W2^T)*(1-h1^2)   (4 rows x 32 cols) ===
        {
            float acc[4] = {0.f, 0.f, 0.f, 0.f};
            #pragma unroll 8
            for (int kk = 0; kk < 16; kk++) {
                float4 gv[4];
                #pragma unroll
                for (int r = 0; r < 4; r++)
                    gv[r] = *(const float4*)&G2s[(rbase + r) * 64 + kk * 4];
                #pragma unroll
                for (int q = 0; q < 4; q++) {
                    // column access: stride 65 == 1 (mod 32) -> conflict-free
                    float w = W2[j1 * W2_STRIDE + kk * 4 + q];
                    #pragma unroll
                    for (int r = 0; r < 4; r++)
                        acc[r] = fmaf((&gv[r].x)[q], w, acc[r]);
                }
            }
            #pragma unroll
            for (int r = 0; r < 4; r++)   // h1 reused from registers (same owner)
                G1s[(rbase + r) * 128 + j1] = acc[r] * (1.0f - h1v[r] * h1v[r]);
        }
        asm volatile("bar.sync %0, %1;" :: "r"(barid), "r"(128) : "memory");

        // ======== phase 4: dy = g1 @ W1[:64,:]^T ; y update (2 rows x 32) ===
        {
            float acc[2] = {0.f, 0.f};
            #pragma unroll 8
            for (int kk = 0; kk < 32; kk++) {
                float4 gv[2];
                #pragma unroll
                for (int r = 0; r < 2; r++)
                    gv[r] = *(const float4*)&G1s[(rbase + rp + r) * 128 + kk * 4];
                #pragma unroll
                for (int q = 0; q < 4; q++) {
                    // column access: stride 129 == 1 (mod 32) -> conflict-free
                    float w = W1[cb * W1_STRIDE + kk * 4 + q];
                    #pragma unroll
                    for (int r = 0; r < 2; r++)
                        acc[r] = fmaf((&gv[r].x)[q], w, acc[r]);
                }
            }
            #pragma unroll
            for (int r = 0; r < 2; r++) {
                int r8 = rbase + rp + r;
                int b = rowTop + r8;
                float ynew = fmaf(-acc[r], hstep, Y[r8 * 64 + cb]) + zsc[r];
                Y[r8 * 64 + cb] = ynew;
                out[((size_t)b * SS + (s + 1)) * HH + cb] = ynew;
            }
        }
        asm volatile("bar.sync %0, %1;" :: "r"(barid), "r"(128) : "memory");
    }
}

// ---------------------------------------------------------------------------
extern "C" void kernel_launch(void* const* d_in, const int* in_sizes, int n_in,
                              void* d_out, int out_size)
{
    (void)in_sizes; (void)n_in; (void)out_size;
    const float* ts    = (const float*)d_in[0];   // time_series (B,S,3)
    const float* noise = (const float*)d_in[1];   // (S-1,B,H)
    const float* Wp1   = (const float*)d_in[2];   // (65,128)
    const float* bp1   = (const float*)d_in[3];   // (128,)
    const float* Wp2   = (const float*)d_in[4];   // (128,64)
    const float* bp2   = (const float*)d_in[5];   // (64,)
    const float* Wp3   = (const float*)d_in[6];   // (64,1)
    // d_in[7] = bp3 (unused: constant shift, zero gradient)
    const float* Wd1   = (const float*)d_in[8];   // (1,32)
    const float* bd1   = (const float*)d_in[9];   // (32,)
    const float* Wd2   = (const float*)d_in[10];  // (32,64)
    const float* bd2   = (const float*)d_in[11];  // (64,)
    const float* mn    = (const float*)d_in[12];  // scalar
    const float* mx    = (const float*)d_in[13];  // scalar
    float* out = (float*)d_out;

    cudaFuncSetAttribute(sde_scan_kernel,
                         cudaFuncAttributeMaxDynamicSharedMemorySize, SMEM_BYTES);

    sigma_kernel<<<SM1, HH>>>(ts, Wd1, bd1, Wd2, bd2, mn, mx);
    sde_scan_kernel<<<BB / 8, 256, SMEM_BYTES>>>(ts, noise, Wp1, bp1, Wp2, bp2, Wp3, out);
}

// round 6
// speedup vs baseline: 1.4841x; 1.4841x over previous
#include <cuda_runtime.h>
#include <cstdint>

// Problem constants (LangevinSDEContiformer: B=1024, S=512, H=64, D_IN=3)
#define BB   1024
#define SS   512
#define HH   64
#define DIN  3
#define SM1  511    // S-1 steps

__device__ float d_sigsc[SM1 * HH];
__device__ float d_hstep[SM1];
__device__ float d_times[SM1];

__global__ void sigma_kernel(const float* __restrict__ ts,
                             const float* __restrict__ Wd1, const float* __restrict__ bd1,
                             const float* __restrict__ Wd2, const float* __restrict__ bd2,
                             const float* __restrict__ minp, const float* __restrict__ maxp)
{
    __shared__ float hh[32];
    int s = blockIdx.x;
    int tid = threadIdx.x;
    float t = ts[(size_t)s * DIN];
    if (tid < 32) hh[tid] = fmaxf(t * Wd1[tid] + bd1[tid], 0.0f);
    __syncthreads();
    float acc = bd2[tid];
    #pragma unroll
    for (int i = 0; i < 32; i++) acc += hh[i] * Wd2[i * HH + tid];
    float sp = fmaxf(acc, 0.0f) + log1pf(expf(-fabsf(acc)));
    float mind = fabsf(minp[0]);
    float maxd = fabsf(maxp[0]);
    float sig = fminf(fmaxf(sp + mind, mind), maxd);
    float hs = ts[(size_t)(s + 1) * DIN] - t;
    d_sigsc[s * HH + tid] = sig * sqrtf(hs);
    if (tid == 0) { d_hstep[s] = hs; d_times[s] = t; }
}

// ---------------------------------------------------------------------------
// f32x2 / bf16x2 helpers
// ---------------------------------------------------------------------------
typedef unsigned long long u64;

__device__ __forceinline__ void fma2(u64& acc, u64 a, u64 b) {
    asm("fma.rn.f32x2 %0, %1, %2, %0;" : "+l"(acc) : "l"(a), "l"(b));
}
__device__ __forceinline__ u64 add2(u64 a, u64 b) {
    u64 r; asm("add.rn.f32x2 %0, %1, %2;" : "=l"(r) : "l"(a), "l"(b)); return r;
}
__device__ __forceinline__ u64 pk2(float lo, float hi) {
    u64 r;
    asm("mov.b64 %0, {%1, %2};" : "=l"(r) : "r"(__float_as_uint(lo)), "r"(__float_as_uint(hi)));
    return r;
}
__device__ __forceinline__ float fold2(u64 p) {
    unsigned int lo, hi;
    asm("mov.b64 {%0, %1}, %2;" : "=r"(lo), "=r"(hi) : "l"(p));
    return __uint_as_float(lo) + __uint_as_float(hi);
}
// bf16x2 word (lo = k-even, hi = k-odd) -> f32x2 pair
__device__ __forceinline__ u64 bfup(unsigned int u) {
    u64 r;
    asm("mov.b64 %0, {%1, %2};" : "=l"(r) : "r"(u << 16), "r"(u & 0xffff0000u));
    return r;
}
// pack two f32 -> bf16x2 (lo in low half)
__device__ __forceinline__ unsigned int packbf(float lo, float hi) {
    unsigned int r;
    asm("cvt.rn.bf16x2.f32 %0, %1, %2;" : "=r"(r) : "f"(hi), "f"(lo));
    return r;
}
__device__ __forceinline__ float tanh_fast(float x) {
    float y;
    asm("tanh.approx.f32 %0, %1;" : "=f"(y) : "f"(x));
    return y;
}

// ---------------------------------------------------------------------------
// Shared layout (in 4-byte words)
// ---------------------------------------------------------------------------
#define OFF_WB1   0                      // [32][128] u32  bf16x2 pairs along k (W1 fwd)
#define OFF_WB2   (OFF_WB1 + 4096)       // [64][64]  u32  pairs along k (W2 fwd)
#define OFF_WB2T  (OFF_WB2 + 4096)       // [32][128] u32  pairs along j (W2^T bwd)
#define OFF_WB1T  (OFF_WB2T + 4096)      // [64][64]  u32  pairs along i (W1^T bwd)
#define OFF_W1T   (OFF_WB1T + 4096)      // [128] f32  t-row of W1
#define OFF_B1    (OFF_W1T + 128)        // [128]
#define OFF_B2    (OFF_B1 + 128)         // [64]
#define OFF_W3    (OFF_B2 + 64)          // [64]
#define OFF_Y     (OFF_W3 + 64)          // [8][64] f32
#define OFF_H1    (OFF_Y + 512)          // [8][128] f32
#define OFF_G2    (OFF_H1 + 1024)        // [8][64] f32
#define OFF_G1    (OFF_G2 + 512)         // [8][128] f32
#define OFF_PART  (OFF_G1 + 1024)        // [32][128] f32x2 pairs (8B) = 8192 words
#define SMEM_WORDS (OFF_PART + 8192)
#define SMEM_BYTES (SMEM_WORDS * 4)      // ~112 KB

__global__ void __launch_bounds__(256, 1)
sde_scan_kernel(const float* __restrict__ ts, const float* __restrict__ noise,
                const float* __restrict__ Wp1, const float* __restrict__ bp1,
                const float* __restrict__ Wp2, const float* __restrict__ bp2,
                const float* __restrict__ Wp3, float* __restrict__ out)
{
    extern __shared__ unsigned int smu[];
    unsigned int* Wb1  = smu + OFF_WB1;
    unsigned int* Wb2  = smu + OFF_WB2;
    unsigned int* Wb2t = smu + OFF_WB2T;
    unsigned int* Wb1t = smu + OFF_WB1T;
    float* W1t = (float*)(smu + OFF_W1T);
    float* B1s = (float*)(smu + OFF_B1);
    float* B2s = (float*)(smu + OFF_B2);
    float* W3s = (float*)(smu + OFF_W3);
    float* Y   = (float*)(smu + OFF_Y);
    float* H1s = (float*)(smu + OFF_H1);
    float* G2s = (float*)(smu + OFF_G2);
    float* G1s = (float*)(smu + OFF_G1);
    u64*   PART= (u64*)(smu + OFF_PART);

    const int tid  = threadIdx.x;
    const int lane = tid & 31;
    const int wid  = tid >> 5;
    const int g    = wid >> 2;          // row group 0/1 (4 rows each)
    const int p    = wid & 3;           // k-split parity 0..3
    const int gtid = tid & 127;         // thread id within group
    const int rbase = g * 4;
    const int rowTop = blockIdx.x * 8;
    const int barid = g + 1;

    // ---- pack weights into shared (bf16x2, k-pairs / transposed variants)
    for (int i = tid; i < 4096; i += 256) {           // Wb1[k2][j]
        int k2 = i >> 7, j = i & 127;
        Wb1[i] = packbf(Wp1[(2 * k2) * 128 + j], Wp1[(2 * k2 + 1) * 128 + j]);
    }
    for (int i = tid; i < 4096; i += 256) {           // Wb2[k2][j]
        int k2 = i >> 6, j = i & 63;
        Wb2[i] = packbf(Wp2[(2 * k2) * 64 + j], Wp2[(2 * k2 + 1) * 64 + j]);
    }
    for (int i = tid; i < 4096; i += 256) {           // Wb2t[j2][i] (pairs along j)
        int j2 = i >> 7, ii = i & 127;
        Wb2t[i] = packbf(Wp2[ii * 64 + 2 * j2], Wp2[ii * 64 + 2 * j2 + 1]);
    }
    for (int i = tid; i < 4096; i += 256) {           // Wb1t[i2][kout] (pairs along i)
        int i2 = i >> 6, ko = i & 63;
        Wb1t[i] = packbf(Wp1[ko * 128 + 2 * i2], Wp1[ko * 128 + 2 * i2 + 1]);
    }
    if (tid < 128) { W1t[tid] = Wp1[64 * 128 + tid]; B1s[tid] = bp1[tid]; }
    if (tid < 64)  { B2s[tid] = bp2[tid]; W3s[tid] = Wp3[tid]; }

    // ---- init y0 and write out[:,0,:]
    #pragma unroll
    for (int q = 0; q < 2; q++) {
        int e = q * 256 + tid;
        int k = e & 63, r8 = e >> 6;
        int b = rowTop + r8;
        float v = (k < DIN) ? ts[(size_t)b * SS * DIN + k] : 0.0f;
        Y[r8 * 64 + k] = v;
        out[((size_t)b * SS) * HH + k] = v;
    }
    __syncthreads();

    for (int s = 0; s < SM1; s++) {
        const float tcur  = d_times[s];
        const float hstep = d_hstep[s];

        // prefetch noise*sigma for this thread's phase-4 outputs (group-local map)
        float zsc[2];
        #pragma unroll
        for (int q = 0; q < 2; q++) {
            int e = q * 128 + gtid;
            int k = e & 63, r = e >> 6;
            int b = rowTop + rbase + r;
            zsc[q] = d_sigsc[s * HH + k] * noise[((size_t)s * BB + b) * HH + k];
        }

        // ======== phase 1 matmul: [y] @ W1, 4 rows x 128 cols, k-split-4 ====
        {
            u64 acc[4][4];
            #pragma unroll
            for (int r = 0; r < 4; r++)
                #pragma unroll
                for (int m = 0; m < 4; m++) acc[r][m] = 0ull;
            #pragma unroll
            for (int it = 0; it < 4; it++) {
                const int k0 = p * 16 + it * 4;
                float4 yv[4];
                #pragma unroll
                for (int r = 0; r < 4; r++)
                    yv[r] = *(const float4*)&Y[(rbase + r) * 64 + k0];
                #pragma unroll
                for (int sub = 0; sub < 2; sub++) {
                    const int k2 = p * 8 + it * 2 + sub;
                    u64 wp[4];
                    #pragma unroll
                    for (int m = 0; m < 4; m++)
                        wp[m] = bfup(Wb1[k2 * 128 + lane + 32 * m]);
                    #pragma unroll
                    for (int r = 0; r < 4; r++) {
                        u64 ap = sub ? pk2(yv[r].z, yv[r].w) : pk2(yv[r].x, yv[r].y);
                        #pragma unroll
                        for (int m = 0; m < 4; m++) fma2(acc[r][m], ap, wp[m]);
                    }
                }
            }
            #pragma unroll
            for (int r = 0; r < 4; r++)
                #pragma unroll
                for (int m = 0; m < 4; m++)
                    PART[((g * 4 + p) * 4 + r) * 128 + lane + 32 * m] = acc[r][m];
        }
        asm volatile("bar.sync %0, %1;" :: "r"(barid), "r"(128) : "memory");
        // combine: h1 = tanh(sum + t*W1t + b1)
        #pragma unroll
        for (int q = 0; q < 4; q++) {
            int e = q * 128 + gtid;
            int j = e & 127, r = e >> 7;
            u64 s2 = add2(add2(PART[((g * 4 + 0) * 4 + r) * 128 + j],
                               PART[((g * 4 + 1) * 4 + r) * 128 + j]),
                          add2(PART[((g * 4 + 2) * 4 + r) * 128 + j],
                               PART[((g * 4 + 3) * 4 + r) * 128 + j]));
            float v = fold2(s2) + fmaf(tcur, W1t[j], B1s[j]);
            H1s[(rbase + r) * 128 + j] = tanh_fast(v);
        }
        asm volatile("bar.sync %0, %1;" :: "r"(barid), "r"(128) : "memory");

        // ======== phase 2 matmul: h1 @ W2, 4 rows x 64 cols, k-split-4 ======
        {
            u64 acc[4][2];
            #pragma unroll
            for (int r = 0; r < 4; r++) { acc[r][0] = 0ull; acc[r][1] = 0ull; }
            #pragma unroll
            for (int it = 0; it < 8; it++) {
                const int k0 = p * 32 + it * 4;
                float4 hv[4];
                #pragma unroll
                for (int r = 0; r < 4; r++)
                    hv[r] = *(const float4*)&H1s[(rbase + r) * 128 + k0];
                #pragma unroll
                for (int sub = 0; sub < 2; sub++) {
                    const int k2 = p * 16 + it * 2 + sub;
                    u64 wp[2];
                    #pragma unroll
                    for (int m = 0; m < 2; m++)
                        wp[m] = bfup(Wb2[k2 * 64 + lane + 32 * m]);
                    #pragma unroll
                    for (int r = 0; r < 4; r++) {
                        u64 ap = sub ? pk2(hv[r].z, hv[r].w) : pk2(hv[r].x, hv[r].y);
                        #pragma unroll
                        for (int m = 0; m < 2; m++) fma2(acc[r][m], ap, wp[m]);
                    }
                }
            }
            #pragma unroll
            for (int r = 0; r < 4; r++)
                #pragma unroll
                for (int m = 0; m < 2; m++)
                    PART[((g * 4 + p) * 4 + r) * 128 + lane + 32 * m] = acc[r][m];
        }
        asm volatile("bar.sync %0, %1;" :: "r"(barid), "r"(128) : "memory");
        // combine: g2 = W3*(1 - tanh(sum+b2)^2)
        #pragma unroll
        for (int q = 0; q < 2; q++) {
            int e = q * 128 + gtid;
            int j = e & 63, r = e >> 6;
            u64 s2 = add2(add2(PART[((g * 4 + 0) * 4 + r) * 128 + j],
                               PART[((g * 4 + 1) * 4 + r) * 128 + j]),
                          add2(PART[((g * 4 + 2) * 4 + r) * 128 + j],
                               PART[((g * 4 + 3) * 4 + r) * 128 + j]));
            float h2 = tanh_fast(fold2(s2) + B2s[j]);
            G2s[(rbase + r) * 64 + j] = W3s[j] * (1.0f - h2 * h2);
        }
        asm volatile("bar.sync %0, %1;" :: "r"(barid), "r"(128) : "memory");

        // ======== phase 3 matmul: g2 @ W2^T, 4 rows x 128 cols, j-split-4 ===
        {
            u64 acc[4][4];
            #pragma unroll
            for (int r = 0; r < 4; r++)
                #pragma unroll
                for (int m = 0; m < 4; m++) acc[r][m] = 0ull;
            #pragma unroll
            for (int it = 0; it < 4; it++) {
                const int j0 = p * 16 + it * 4;
                float4 gv[4];
                #pragma unroll
                for (int r = 0; r < 4; r++)
                    gv[r] = *(const float4*)&G2s[(rbase + r) * 64 + j0];
                #pragma unroll
                for (int sub = 0; sub < 2; sub++) {
                    const int j2 = p * 8 + it * 2 + sub;
                    u64 wp[4];
                    #pragma unroll
                    for (int m = 0; m < 4; m++)
                        wp[m] = bfup(Wb2t[j2 * 128 + lane + 32 * m]);
                    #pragma unroll
                    for (int r = 0; r < 4; r++) {
                        u64 ap = sub ? pk2(gv[r].z, gv[r].w) : pk2(gv[r].x, gv[r].y);
                        #pragma unroll
                        for (int m = 0; m < 4; m++) fma2(acc[r][m], ap, wp[m]);
                    }
                }
            }
            #pragma unroll
            for (int r = 0; r < 4; r++)
                #pragma unroll
                for (int m = 0; m < 4; m++)
                    PART[((g * 4 + p) * 4 + r) * 128 + lane + 32 * m] = acc[r][m];
        }
        asm volatile("bar.sync %0, %1;" :: "r"(barid), "r"(128) : "memory");
        // combine: g1 = sum * (1 - h1^2)
        #pragma unroll
        for (int q = 0; q < 4; q++) {
            int e = q * 128 + gtid;
            int i = e & 127, r = e >> 7;
            u64 s2 = add2(add2(PART[((g * 4 + 0) * 4 + r) * 128 + i],
                               PART[((g * 4 + 1) * 4 + r) * 128 + i]),
                          add2(PART[((g * 4 + 2) * 4 + r) * 128 + i],
                               PART[((g * 4 + 3) * 4 + r) * 128 + i]));
            float h1v = H1s[(rbase + r) * 128 + i];
            G1s[(rbase + r) * 128 + i] = fold2(s2) * (1.0f - h1v * h1v);
        }
        asm volatile("bar.sync %0, %1;" :: "r"(barid), "r"(128) : "memory");

        // ======== phase 4 matmul: g1 @ W1^T, 4 rows x 64 cols, i-split-4 ====
        {
            u64 acc[4][2];
            #pragma unroll
            for (int r = 0; r < 4; r++) { acc[r][0] = 0ull; acc[r][1] = 0ull; }
            #pragma unroll
            for (int it = 0; it < 8; it++) {
                const int i0 = p * 32 + it * 4;
                float4 gv[4];
                #pragma unroll
                for (int r = 0; r < 4; r++)
                    gv[r] = *(const float4*)&G1s[(rbase + r) * 128 + i0];
                #pragma unroll
                for (int sub = 0; sub < 2; sub++) {
                    const int i2 = p * 16 + it * 2 + sub;
                    u64 wp[2];
                    #pragma unroll
                    for (int m = 0; m < 2; m++)
                        wp[m] = bfup(Wb1t[i2 * 64 + lane + 32 * m]);
                    #pragma unroll
                    for (int r = 0; r < 4; r++) {
                        u64 ap = sub ? pk2(gv[r].z, gv[r].w) : pk2(gv[r].x, gv[r].y);
                        #pragma unroll
                        for (int m = 0; m < 2; m++) fma2(acc[r][m], ap, wp[m]);
                    }
                }
            }
            #pragma unroll
            for (int r = 0; r < 4; r++)
                #pragma unroll
                for (int m = 0; m < 2; m++)
                    PART[((g * 4 + p) * 4 + r) * 128 + lane + 32 * m] = acc[r][m];
        }
        asm volatile("bar.sync %0, %1;" :: "r"(barid), "r"(128) : "memory");
        // combine: y += -dy*h + sig*z*sqrt(h); write out
        #pragma unroll
        for (int q = 0; q < 2; q++) {
            int e = q * 128 + gtid;
            int k = e & 63, r = e >> 6;
            u64 s2 = add2(add2(PART[((g * 4 + 0) * 4 + r) * 128 + k],
                               PART[((g * 4 + 1) * 4 + r) * 128 + k]),
                          add2(PART[((g * 4 + 2) * 4 + r) * 128 + k],
                               PART[((g * 4 + 3) * 4 + r) * 128 + k]));
            float dy = fold2(s2);
            int r8 = rbase + r;
            int b = rowTop + r8;
            float ynew = fmaf(-dy, hstep, Y[r8 * 64 + k]) + zsc[q];
            Y[r8 * 64 + k] = ynew;
            out[((size_t)b * SS + (s + 1)) * HH + k] = ynew;
        }
        asm volatile("bar.sync %0, %1;" :: "r"(barid), "r"(128) : "memory");
    }
}

// ---------------------------------------------------------------------------
extern "C" void kernel_launch(void* const* d_in, const int* in_sizes, int n_in,
                              void* d_out, int out_size)
{
    (void)in_sizes; (void)n_in; (void)out_size;
    const float* ts    = (const float*)d_in[0];   // time_series (B,S,3)
    const float* noise = (const float*)d_in[1];   // (S-1,B,H)
    const float* Wp1   = (const float*)d_in[2];   // (65,128)
    const float* bp1   = (const float*)d_in[3];   // (128,)
    const float* Wp2   = (const float*)d_in[4];   // (128,64)
    const float* bp2   = (const float*)d_in[5];   // (64,)
    const float* Wp3   = (const float*)d_in[6];   // (64,1)
    // d_in[7] = bp3 (unused: constant shift, zero gradient)
    const float* Wd1   = (const float*)d_in[8];   // (1,32)
    const float* bd1   = (const float*)d_in[9];   // (32,)
    const float* Wd2   = (const float*)d_in[10];  // (32,64)
    const float* bd2   = (const float*)d_in[11];  // (64,)
    const float* mn    = (const float*)d_in[12];  // scalar
    const float* mx    = (const float*)d_in[13];  // scalar
    float* out = (float*)d_out;

    cudaFuncSetAttribute(sde_scan_kernel,
                         cudaFuncAttributeMaxDynamicSharedMemorySize, SMEM_BYTES);

    sigma_kernel<<<SM1, HH>>>(ts, Wd1, bd1, Wd2, bd2, mn, mx);
    sde_scan_kernel<<<BB / 8, 256, SMEM_BYTES>>>(ts, noise, Wp1, bp1, Wp2, bp2, Wp3, out);
}